// round 1
// baseline (speedup 1.0000x reference)
#include <cuda_runtime.h>

#define N_NODES 1048576
#define N_EDGES (4 * N_NODES)

// Scratch accumulator: per-node (sum0, sum1, sum2, count). 16 MB device global.
__device__ float4 g_scr[N_NODES];

__global__ void zero_kernel() {
    int i = blockIdx.x * blockDim.x + threadIdx.x;
    if (i < N_NODES) g_scr[i] = make_float4(0.f, 0.f, 0.f, 0.f);
}

// Edge MLP + scatter-add. One thread per edge.
// hidden_j = relu(b1a[j] + x0*w1a[0][j] + x1*w1a[1][j] + x2*w1a[2][j] + ea*w1a[3][j])
// out_k    = b1b[k] + sum_j hidden_j * w1b[j][k]
__global__ void edge_kernel(const float* __restrict__ x,
                            const int*   __restrict__ ei,
                            const float* __restrict__ eattr,
                            const float* __restrict__ w1a,
                            const float* __restrict__ b1a,
                            const float* __restrict__ w1b,
                            const float* __restrict__ b1b) {
    __shared__ float4 sw[20];  // column j of w1a (4 input weights)
    __shared__ float4 sv[20];  // (b1a[j], w1b[j][0], w1b[j][1], w1b[j][2])
    int t = threadIdx.x;
    if (t < 20) {
        sw[t] = make_float4(w1a[t], w1a[20 + t], w1a[40 + t], w1a[60 + t]);
        sv[t] = make_float4(b1a[t], w1b[3 * t], w1b[3 * t + 1], w1b[3 * t + 2]);
    }
    __syncthreads();

    int e = blockIdx.x * blockDim.x + t;
    if (e >= N_EDGES) return;

    int r = ei[e];            // source node (row)
    int c = ei[N_EDGES + e];  // destination node (col)

    float x0 = __ldg(&x[3 * r]);
    float x1 = __ldg(&x[3 * r + 1]);
    float x2 = __ldg(&x[3 * r + 2]);
    float ea = eattr[e];

    float o0 = b1b[0], o1 = b1b[1], o2 = b1b[2];
#pragma unroll
    for (int j = 0; j < 20; j++) {
        float4 w = sw[j];
        float4 v = sv[j];
        float h = fmaf(x0, w.x, fmaf(x1, w.y, fmaf(x2, w.z, fmaf(ea, w.w, v.x))));
        h = fmaxf(h, 0.f);
        o0 = fmaf(h, v.y, o0);
        o1 = fmaf(h, v.z, o1);
        o2 = fmaf(h, v.w, o2);
    }

    // One vectorized reduction per edge: (sum0, sum1, sum2, count)
    float4* dst = &g_scr[c];
    asm volatile("red.global.add.v4.f32 [%0], {%1, %2, %3, %4};"
                 :: "l"(dst), "f"(o0), "f"(o1), "f"(o2), "f"(1.0f)
                 : "memory");
}

// Node MLP + L2 normalize. One thread per node.
__global__ void node_kernel(const float* __restrict__ x,
                            const float* __restrict__ w2a,
                            const float* __restrict__ b2a,
                            const float* __restrict__ w2b,
                            const float* __restrict__ b2b,
                            float* __restrict__ out) {
    __shared__ float4 sa[20];  // w2a rows 0..3, column j
    __shared__ float4 sb[20];  // (w2a[4][j], w2a[5][j], b2a[j], -)
    __shared__ float4 sc[20];  // (w2b[j][0..2], -)
    int t = threadIdx.x;
    if (t < 20) {
        sa[t] = make_float4(w2a[t], w2a[20 + t], w2a[40 + t], w2a[60 + t]);
        sb[t] = make_float4(w2a[80 + t], w2a[100 + t], b2a[t], 0.f);
        sc[t] = make_float4(w2b[3 * t], w2b[3 * t + 1], w2b[3 * t + 2], 0.f);
    }
    __syncthreads();

    int i = blockIdx.x * blockDim.x + t;
    if (i >= N_NODES) return;

    float4 s = g_scr[i];
    float inv = 1.0f / fmaxf(s.w, 1.0f);
    float a0 = s.x * inv, a1 = s.y * inv, a2 = s.z * inv;
    float x0 = x[3 * i], x1 = x[3 * i + 1], x2 = x[3 * i + 2];

    float o0 = b2b[0], o1 = b2b[1], o2 = b2b[2];
#pragma unroll
    for (int j = 0; j < 20; j++) {
        float4 wa = sa[j];
        float4 wb = sb[j];
        float4 wc = sc[j];
        float h = fmaf(x0, wa.x,
                  fmaf(x1, wa.y,
                  fmaf(x2, wa.z,
                  fmaf(a0, wa.w,
                  fmaf(a1, wb.x,
                  fmaf(a2, wb.y, wb.z))))));
        h = fmaxf(h, 0.f);
        o0 = fmaf(h, wc.x, o0);
        o1 = fmaf(h, wc.y, o1);
        o2 = fmaf(h, wc.z, o2);
    }

    float fac = rsqrtf(o0 * o0 + o1 * o1 + o2 * o2);
    out[3 * i]     = o0 * fac;
    out[3 * i + 1] = o1 * fac;
    out[3 * i + 2] = o2 * fac;
}

extern "C" void kernel_launch(void* const* d_in, const int* in_sizes, int n_in,
                              void* d_out, int out_size) {
    // Input order per reference setup_inputs:
    // 0:x 1:edge_index 2:edge_attr 3:u 4:batch
    // 5:w1a 6:b1a 7:w1b 8:b1b 9:w2a 10:b2a 11:w2b 12:b2b
    const float* x     = (const float*)d_in[0];
    const int*   ei    = (const int*)  d_in[1];
    const float* eattr = (const float*)d_in[2];
    const float* w1a   = (const float*)d_in[5];
    const float* b1a   = (const float*)d_in[6];
    const float* w1b   = (const float*)d_in[7];
    const float* b1b   = (const float*)d_in[8];
    const float* w2a   = (const float*)d_in[9];
    const float* b2a   = (const float*)d_in[10];
    const float* w2b   = (const float*)d_in[11];
    const float* b2b   = (const float*)d_in[12];
    float* out = (float*)d_out;

    zero_kernel<<<N_NODES / 256, 256>>>();
    edge_kernel<<<N_EDGES / 256, 256>>>(x, ei, eattr, w1a, b1a, w1b, b1b);
    node_kernel<<<N_NODES / 256, 256>>>(x, w2a, b2a, w2b, b2b, out);
}

// round 2
// speedup vs baseline: 1.0226x; 1.0226x over previous
#include <cuda_runtime.h>

#define N_NODES 1048576
#define N_EDGES (4 * N_NODES)

typedef unsigned long long u64;

// Scratch: per-node (sum0,sum1,sum2,count) + padded x. 32 MB device globals.
__device__ float4 g_scr[N_NODES];
__device__ float4 g_x4[N_NODES];

__device__ __forceinline__ u64 fma2(u64 a, u64 b, u64 c) {
    u64 d;
    asm("fma.rn.f32x2 %0, %1, %2, %3;" : "=l"(d) : "l"(a), "l"(b), "l"(c));
    return d;
}
__device__ __forceinline__ u64 pack2(float lo, float hi) {
    u64 d;
    asm("mov.b64 %0, {%1, %2};" : "=l"(d) : "f"(lo), "f"(hi));
    return d;
}
__device__ __forceinline__ void unpack2(u64 a, float& lo, float& hi) {
    asm("mov.b64 {%0, %1}, %2;" : "=f"(lo), "=f"(hi) : "l"(a));
}
__device__ __forceinline__ u64 relu2(u64 a) {
    float lo, hi;
    unpack2(a, lo, hi);
    return pack2(fmaxf(lo, 0.f), fmaxf(hi, 0.f));
}

// Zero scratch + pad x[N,3] into float4 table.
__global__ void prep_kernel(const float* __restrict__ x) {
    int i = blockIdx.x * blockDim.x + threadIdx.x;
    if (i < N_NODES) {
        g_scr[i] = make_float4(0.f, 0.f, 0.f, 0.f);
        g_x4[i] = make_float4(x[3 * i], x[3 * i + 1], x[3 * i + 2], 0.f);
    }
}

// Edge MLP + scatter-add. TWO edges per thread, packed f32x2 math.
__global__ void __launch_bounds__(256) edge_kernel(
        const int*   __restrict__ ei,
        const float* __restrict__ eattr,
        const float* __restrict__ w1a,
        const float* __restrict__ b1a,
        const float* __restrict__ w1b,
        const float* __restrict__ b1b) {
    // per hidden j: [wx, wy, wz, ww, bias, v0, v1, v2], each scalar duplicated.
    __shared__ __align__(16) u64 sw[20][8];
    int t = threadIdx.x;
    if (t < 20) {
        sw[t][0] = pack2(w1a[t],          w1a[t]);
        sw[t][1] = pack2(w1a[20 + t],     w1a[20 + t]);
        sw[t][2] = pack2(w1a[40 + t],     w1a[40 + t]);
        sw[t][3] = pack2(w1a[60 + t],     w1a[60 + t]);
        sw[t][4] = pack2(b1a[t],          b1a[t]);
        sw[t][5] = pack2(w1b[3 * t],      w1b[3 * t]);
        sw[t][6] = pack2(w1b[3 * t + 1],  w1b[3 * t + 1]);
        sw[t][7] = pack2(w1b[3 * t + 2],  w1b[3 * t + 2]);
    }
    __syncthreads();

    int e = (blockIdx.x * 256 + t) * 2;
    if (e >= N_EDGES) return;

    int2   rr = *(const int2*)(ei + e);             // source nodes
    int2   cc = *(const int2*)(ei + N_EDGES + e);   // destination nodes
    float2 ef = *(const float2*)(eattr + e);

    float4 xa = g_x4[rr.x];
    float4 xb = g_x4[rr.y];

    u64 X0 = pack2(xa.x, xb.x);
    u64 X1 = pack2(xa.y, xb.y);
    u64 X2 = pack2(xa.z, xb.z);
    u64 EA = pack2(ef.x, ef.y);

    float bb0 = b1b[0], bb1 = b1b[1], bb2 = b1b[2];
    u64 o0 = pack2(bb0, bb0);
    u64 o1 = pack2(bb1, bb1);
    u64 o2 = pack2(bb2, bb2);

#pragma unroll
    for (int j = 0; j < 20; j++) {
        const u64* w = sw[j];
        u64 h = fma2(X0, w[0], fma2(X1, w[1], fma2(X2, w[2], fma2(EA, w[3], w[4]))));
        h = relu2(h);
        o0 = fma2(h, w[5], o0);
        o1 = fma2(h, w[6], o1);
        o2 = fma2(h, w[7], o2);
    }

    float a0, b0, a1, b1v, a2, b2v;
    unpack2(o0, a0, b0);
    unpack2(o1, a1, b1v);
    unpack2(o2, a2, b2v);

    asm volatile("red.global.add.v4.f32 [%0], {%1, %2, %3, %4};"
                 :: "l"(g_scr + cc.x), "f"(a0), "f"(a1), "f"(a2), "f"(1.0f) : "memory");
    asm volatile("red.global.add.v4.f32 [%0], {%1, %2, %3, %4};"
                 :: "l"(g_scr + cc.y), "f"(b0), "f"(b1v), "f"(b2v), "f"(1.0f) : "memory");
}

// Node MLP + L2 normalize. TWO nodes per thread, packed f32x2 math.
__global__ void __launch_bounds__(256) node_kernel(
        const float* __restrict__ w2a,
        const float* __restrict__ b2a,
        const float* __restrict__ w2b,
        const float* __restrict__ b2b,
        float* __restrict__ out) {
    // per hidden j: [w0..w5, bias, v0, v1, v2], duplicated. Row = 80B (16B-aligned).
    __shared__ __align__(16) u64 sw[20][10];
    int t = threadIdx.x;
    if (t < 20) {
        sw[t][0] = pack2(w2a[t],           w2a[t]);
        sw[t][1] = pack2(w2a[20 + t],      w2a[20 + t]);
        sw[t][2] = pack2(w2a[40 + t],      w2a[40 + t]);
        sw[t][3] = pack2(w2a[60 + t],      w2a[60 + t]);
        sw[t][4] = pack2(w2a[80 + t],      w2a[80 + t]);
        sw[t][5] = pack2(w2a[100 + t],     w2a[100 + t]);
        sw[t][6] = pack2(b2a[t],           b2a[t]);
        sw[t][7] = pack2(w2b[3 * t],       w2b[3 * t]);
        sw[t][8] = pack2(w2b[3 * t + 1],   w2b[3 * t + 1]);
        sw[t][9] = pack2(w2b[3 * t + 2],   w2b[3 * t + 2]);
    }
    __syncthreads();

    int i = (blockIdx.x * 256 + t) * 2;
    if (i >= N_NODES) return;

    float4 sA = g_scr[i];
    float4 sB = g_scr[i + 1];
    float4 xA = g_x4[i];
    float4 xB = g_x4[i + 1];

    float invA = 1.0f / fmaxf(sA.w, 1.0f);
    float invB = 1.0f / fmaxf(sB.w, 1.0f);

    u64 X0 = pack2(xA.x, xB.x);
    u64 X1 = pack2(xA.y, xB.y);
    u64 X2 = pack2(xA.z, xB.z);
    u64 A0 = pack2(sA.x * invA, sB.x * invB);
    u64 A1 = pack2(sA.y * invA, sB.y * invB);
    u64 A2 = pack2(sA.z * invA, sB.z * invB);

    float bb0 = b2b[0], bb1 = b2b[1], bb2 = b2b[2];
    u64 o0 = pack2(bb0, bb0);
    u64 o1 = pack2(bb1, bb1);
    u64 o2 = pack2(bb2, bb2);

#pragma unroll
    for (int j = 0; j < 20; j++) {
        const u64* w = sw[j];
        u64 h = fma2(X0, w[0],
                fma2(X1, w[1],
                fma2(X2, w[2],
                fma2(A0, w[3],
                fma2(A1, w[4],
                fma2(A2, w[5], w[6]))))));
        h = relu2(h);
        o0 = fma2(h, w[7], o0);
        o1 = fma2(h, w[8], o1);
        o2 = fma2(h, w[9], o2);
    }

    float pA0, pB0, pA1, pB1, pA2, pB2;
    unpack2(o0, pA0, pB0);
    unpack2(o1, pA1, pB1);
    unpack2(o2, pA2, pB2);

    float facA = rsqrtf(pA0 * pA0 + pA1 * pA1 + pA2 * pA2);
    float facB = rsqrtf(pB0 * pB0 + pB1 * pB1 + pB2 * pB2);

    // 6 consecutive floats starting at out + 6*(i/2); 8B-aligned -> 3x st.v2
    float2* o = (float2*)(out + 3 * i);
    o[0] = make_float2(pA0 * facA, pA1 * facA);
    o[1] = make_float2(pA2 * facA, pB0 * facB);
    o[2] = make_float2(pB1 * facB, pB2 * facB);
}

extern "C" void kernel_launch(void* const* d_in, const int* in_sizes, int n_in,
                              void* d_out, int out_size) {
    // 0:x 1:edge_index 2:edge_attr 3:u 4:batch
    // 5:w1a 6:b1a 7:w1b 8:b1b 9:w2a 10:b2a 11:w2b 12:b2b
    const float* x     = (const float*)d_in[0];
    const int*   ei    = (const int*)  d_in[1];
    const float* eattr = (const float*)d_in[2];
    const float* w1a   = (const float*)d_in[5];
    const float* b1a   = (const float*)d_in[6];
    const float* w1b   = (const float*)d_in[7];
    const float* b1b   = (const float*)d_in[8];
    const float* w2a   = (const float*)d_in[9];
    const float* b2a   = (const float*)d_in[10];
    const float* w2b   = (const float*)d_in[11];
    const float* b2b   = (const float*)d_in[12];
    float* out = (float*)d_out;

    prep_kernel<<<N_NODES / 256, 256>>>(x);
    edge_kernel<<<N_EDGES / 512, 256>>>(ei, eattr, w1a, b1a, w1b, b1b);
    node_kernel<<<N_NODES / 512, 256>>>(w2a, b2a, w2b, b2b, out);
}